// round 1
// baseline (speedup 1.0000x reference)
#include <cuda_runtime.h>
#include <cstddef>

// ---------------- problem constants ----------------
static constexpr int B  = 4;
static constexpr int C  = 512;
static constexpr int T  = 2048;
static constexpr int H  = 8;
static constexpr int FC = 2048;
static constexpr int L  = 6;
static constexpr int KW3 = 3;
static constexpr int S  = 256;
static constexpr int DK = 64;

// ---------------- device scratch (no allocations allowed) ----------------
__device__ float g_x  [B * C  * T];   // activations
__device__ float g_y  [B * C  * T];   // branch output
__device__ float g_q  [B * C  * T];
__device__ float g_k  [B * C  * T];
__device__ float g_v  [B * C  * T];
__device__ float g_att[B * C  * T];   // attention output (pre out-proj)
__device__ float g_h  [B * FC * T];   // ffn hidden

// ---------------- conv-as-GEMM kernel ----------------
// Y[b,o,t] = sum_{c,k} W[o, c, k] * X[b, c, t + k - PL]  (+bias, opt relu/addsrc/mask)
// X: (B, Cin, T) row-major per channel. W: (Cout, Cin, KW). Y: (B, Cout, T).
// Grid: (T/64, Cout/64, B). Block: 256 threads. BM=BN=64, BK=16, 4x4 microtile.
static constexpr int BM = 64, BN = 64, BK = 16;

template <int KW, bool RELU, bool DOMASK, bool ADDSRC>
__global__ __launch_bounds__(256) void conv_gemm(
    const float* __restrict__ X, const float* __restrict__ W,
    const float* __restrict__ bias, const float* __restrict__ src,
    const float* __restrict__ mask, float* __restrict__ Y,
    int Cin, int PL)
{
    constexpr int XW = BN + KW - 1;     // loaded columns
    __shared__ float Ws[KW][BK][68];    // [k][c][o], padded
    __shared__ float Xs[BK][68];        // [c][t+halo], padded (float4-aligned)

    const int b   = blockIdx.z;
    const int om  = blockIdx.y * BM;
    const int tn0 = blockIdx.x * BN;
    const int tid = threadIdx.x;
    const int tx  = tid & 15;           // 16 cols of threads -> t
    const int ty  = tid >> 4;           // 16 rows of threads -> o

    const float* __restrict__ Xb = X + (size_t)b * Cin * T;

    float acc[4][4];
#pragma unroll
    for (int i = 0; i < 4; i++)
#pragma unroll
        for (int j = 0; j < 4; j++) acc[i][j] = 0.f;

    for (int c0 = 0; c0 < Cin; c0 += BK) {
        // --- load W tile (coalesced runs of BK*KW along (c,k)) ---
        for (int idx = tid; idx < BM * BK * KW; idx += 256) {
            int o  = idx / (BK * KW);
            int r  = idx % (BK * KW);
            int cc = r / KW;
            int kk = r % KW;
            Ws[kk][cc][o] = W[(size_t)(om + o) * Cin * KW + (size_t)(c0 + cc) * KW + kk];
        }
        // --- load X tile with halo, bounds-checked (coalesced along t) ---
        for (int idx = tid; idx < BK * XW; idx += 256) {
            int cc  = idx / XW;
            int col = idx % XW;
            int t   = tn0 - PL + col;
            float xv = (t >= 0 && t < T) ? Xb[(size_t)(c0 + cc) * T + t] : 0.f;
            Xs[cc][col] = xv;
        }
        __syncthreads();

#pragma unroll
        for (int cc = 0; cc < BK; cc++) {
            float rnx[4 + KW - 1];
            float4 xv4 = *(const float4*)&Xs[cc][tx * 4];
            rnx[0] = xv4.x; rnx[1] = xv4.y; rnx[2] = xv4.z; rnx[3] = xv4.w;
            if constexpr (KW == 3) {
                rnx[4] = Xs[cc][tx * 4 + 4];
                rnx[5] = Xs[cc][tx * 4 + 5];
            }
#pragma unroll
            for (int kk = 0; kk < KW; kk++) {
                float4 wv = *(const float4*)&Ws[kk][cc][ty * 4];
                float rm[4] = {wv.x, wv.y, wv.z, wv.w};
#pragma unroll
                for (int i = 0; i < 4; i++)
#pragma unroll
                    for (int j = 0; j < 4; j++)
                        acc[i][j] += rm[i] * rnx[j + kk];
            }
        }
        __syncthreads();
    }

    const int Cout = gridDim.y * BM;
#pragma unroll
    for (int i = 0; i < 4; i++) {
        int o = om + ty * 4 + i;
        float bv = bias[o];
#pragma unroll
        for (int j = 0; j < 4; j++) {
            int t = tn0 + tx * 4 + j;
            float vout = acc[i][j] + bv;
            if (RELU) vout = fmaxf(vout, 0.f);
            size_t oi = ((size_t)b * Cout + o) * T + t;
            if (ADDSRC) vout += src[oi];
            if (DOMASK) vout *= mask[(size_t)b * T + t];
            Y[oi] = vout;
        }
    }
}

// ---------------- f0 prenet (Cin=1, K=3, pad 1,1) added in-place ----------------
__global__ void add_f0(const float* __restrict__ f0, const float* __restrict__ w,
                       const float* __restrict__ fb, float* __restrict__ y)
{
    int t = blockIdx.x * 256 + threadIdx.x;
    int c = blockIdx.y;
    int b = blockIdx.z;
    float fm1 = (t - 1 >= 0) ? f0[(size_t)b * T + t - 1] : 0.f;
    float fc0 = f0[(size_t)b * T + t];
    float fp1 = (t + 1 < T) ? f0[(size_t)b * T + t + 1] : 0.f;
    float v = w[c * 3 + 0] * fm1 + w[c * 3 + 1] * fc0 + w[c * 3 + 2] * fp1 + fb[c];
    y[((size_t)b * C + c) * T + t] += v;
}

// ---------------- fused residual-add + LayerNorm over channel dim ----------------
// out[b,:,t] = LN(x[b,:,t] + y[b,:,t]) * g + be   (out may alias x)
__global__ void add_ln(const float* __restrict__ x, const float* __restrict__ y,
                       const float* __restrict__ g, const float* __restrict__ be,
                       float* __restrict__ out)
{
    __shared__ float red0[8][32];
    __shared__ float red1[8][32];
    __shared__ float smv[2][32];
    const int tx = threadIdx.x, ty = threadIdx.y;
    const int t = blockIdx.x * 32 + tx;
    const int b = blockIdx.y;
    const size_t base = (size_t)b * C * T + t;

    float s = 0.f, sq = 0.f;
    for (int c = ty; c < C; c += 8) {
        float v = x[base + (size_t)c * T] + y[base + (size_t)c * T];
        s += v; sq += v * v;
    }
    red0[ty][tx] = s; red1[ty][tx] = sq;
    __syncthreads();
    if (ty == 0) {
#pragma unroll
        for (int i = 1; i < 8; i++) { s += red0[i][tx]; sq += red1[i][tx]; }
        float mean = s * (1.f / C);
        float var  = sq * (1.f / C) - mean * mean;
        smv[0][tx] = mean;
        smv[1][tx] = rsqrtf(var + 1e-5f);
    }
    __syncthreads();
    float mean = smv[0][tx], rstd = smv[1][tx];
    for (int c = ty; c < C; c += 8) {
        float v = x[base + (size_t)c * T] + y[base + (size_t)c * T];
        out[base + (size_t)c * T] = (v - mean) * rstd * g[c] + be[c];
    }
}

// ---------------- fused causal flash attention (fp32) ----------------
// q,k,v,o: (B, C, T) with C = H*DK. Per (b,h): S = (Q K^T)/8, causal mask -1e4,
// softmax, O = P V. BM=BN=64, online softmax. Grid (T/64, B*H), 256 threads.
static constexpr int FLASH_SMEM = (64 * 64 + 64 * 68 + 64 * 68) * 4;  // 51200 B

__global__ __launch_bounds__(256) void flash_attn(
    const float* __restrict__ q, const float* __restrict__ k,
    const float* __restrict__ v, float* __restrict__ o)
{
    extern __shared__ float sm[];
    float* Qs = sm;              // [64][64]  row = query t, col = d
    float* Ks = sm + 64 * 64;    // [64][68]  row = key j,  col = d
    float* Vt = Ks + 64 * 68;    // [64][68]  row = d,      col = key j
    float* Ss = Ks;              // aliases Ks after QK phase: [64(row)][68] probs

    const int tid  = threadIdx.x;
    const int lane = tid & 31;
    const int warp = tid >> 5;
    const int mb   = blockIdx.x;
    const int m0   = mb * 64;
    const int bh   = blockIdx.y;
    const int b    = bh >> 3;
    const int h    = bh & 7;
    const size_t base = ((size_t)b * C + (size_t)h * DK) * T;
    const float* __restrict__ qp = q + base;
    const float* __restrict__ kp = k + base;
    const float* __restrict__ vp = v + base;

    // load Q tile, pre-scaled by 1/sqrt(dk)=1/8
    for (int idx = tid; idx < 64 * 64; idx += 256) {
        int d = idx >> 6, tt = idx & 63;
        Qs[tt * 64 + d] = qp[(size_t)d * T + m0 + tt] * 0.125f;
    }

    float mI[8], lI[8], a0[8], a1[8];
#pragma unroll
    for (int r = 0; r < 8; r++) { mI[r] = -1e30f; lI[r] = 0.f; a0[r] = 0.f; a1[r] = 0.f; }
    const int r0 = warp * 8;     // this warp's 8 query rows (local)

    for (int kbk = 0; kbk <= mb; kbk++) {
        const int kn0 = kbk * 64;
        __syncthreads();  // Q load (iter 0) / prev-iter Ss,Vt readers done
        for (int idx = tid; idx < 64 * 64; idx += 256) {
            int d = idx >> 6, j = idx & 63;
            float kv = kp[(size_t)d * T + kn0 + j];
            float vv = vp[(size_t)d * T + kn0 + j];
            Ks[j * 68 + d] = kv;
            Vt[d * 68 + j] = vv;
        }
        __syncthreads();

        // ---- QK: lane handles keys j=lane and j=lane+32 ----
        float sc0[8], sc1[8];
#pragma unroll
        for (int r = 0; r < 8; r++) {
            int rr = r0 + r;
            float s0 = 0.f, s1 = 0.f;
#pragma unroll
            for (int d = 0; d < 64; d += 4) {
                float4 q4 = *(const float4*)&Qs[rr * 64 + d];
                float4 ka = *(const float4*)&Ks[lane * 68 + d];
                float4 kb = *(const float4*)&Ks[(lane + 32) * 68 + d];
                s0 += q4.x * ka.x + q4.y * ka.y + q4.z * ka.z + q4.w * ka.w;
                s1 += q4.x * kb.x + q4.y * kb.y + q4.z * kb.z + q4.w * kb.w;
            }
            int tg = m0 + rr;
            if (kn0 + lane      > tg) s0 = -1e4f;   // matches reference mask value
            if (kn0 + lane + 32 > tg) s1 = -1e4f;
            sc0[r] = s0; sc1[r] = s1;
        }
        __syncthreads();  // everyone done reading Ks before we overwrite with probs

        // ---- online softmax update; write probs into Ss (alias of Ks) ----
#pragma unroll
        for (int r = 0; r < 8; r++) {
            int rr = r0 + r;
            float mx = fmaxf(sc0[r], sc1[r]);
#pragma unroll
            for (int off = 16; off; off >>= 1)
                mx = fmaxf(mx, __shfl_xor_sync(0xffffffffu, mx, off));
            float mnew = fmaxf(mI[r], mx);
            float p0 = __expf(sc0[r] - mnew);
            float p1 = __expf(sc1[r] - mnew);
            float ps = p0 + p1;
#pragma unroll
            for (int off = 16; off; off >>= 1)
                ps += __shfl_xor_sync(0xffffffffu, ps, off);
            float corr = __expf(mI[r] - mnew);
            lI[r] = lI[r] * corr + ps;
            mI[r] = mnew;
            a0[r] *= corr; a1[r] *= corr;
            Ss[rr * 68 + lane]      = p0;
            Ss[rr * 68 + lane + 32] = p1;
        }
        __syncwarp();  // Ss rows are warp-private

        // ---- PV: lane owns output dims d=lane and d=lane+32 ----
#pragma unroll
        for (int r = 0; r < 8; r++) {
            int rr = r0 + r;
            float acc0 = 0.f, acc1 = 0.f;
#pragma unroll
            for (int j = 0; j < 64; j += 4) {
                float4 p4 = *(const float4*)&Ss[rr * 68 + j];
                float4 va = *(const float4*)&Vt[lane * 68 + j];
                float4 vb = *(const float4*)&Vt[(lane + 32) * 68 + j];
                acc0 += p4.x * va.x + p4.y * va.y + p4.z * va.z + p4.w * va.w;
                acc1 += p4.x * vb.x + p4.y * vb.y + p4.z * vb.z + p4.w * vb.w;
            }
            a0[r] += acc0; a1[r] += acc1;
        }
    }

#pragma unroll
    for (int r = 0; r < 8; r++) {
        int rr = r0 + r;
        float inv = 1.f / lI[r];
        o[base + (size_t)lane        * T + m0 + rr] = a0[r] * inv;
        o[base + (size_t)(lane + 32) * T + m0 + rr] = a1[r] * inv;
    }
}

// ---------------- final 1-channel projection ----------------
__global__ void proj_out(const float* __restrict__ x, const float* __restrict__ w,
                         const float* __restrict__ pb, const float* __restrict__ mask,
                         float* __restrict__ out)
{
    int t = blockIdx.x * 256 + threadIdx.x;
    int b = blockIdx.y;
    float s = pb[0];
    const float* xb = x + (size_t)b * C * T;
    for (int c = 0; c < C; c++)
        s += w[c] * xb[(size_t)c * T + t];
    out[(size_t)b * T + t] = s * mask[(size_t)b * T + t];
}

// ---------------- launch ----------------
extern "C" void kernel_launch(void* const* d_in, const int* in_sizes, int n_in,
                              void* d_out, int out_size)
{
    const float* x    = (const float*)d_in[0];
    const float* f0   = (const float*)d_in[1];
    const float* mask = (const float*)d_in[2];
    const float* spk  = (const float*)d_in[3];
    const float* prw  = (const float*)d_in[4];
    const float* prb  = (const float*)d_in[5];
    const float* f0w  = (const float*)d_in[6];
    const float* f0b  = (const float*)d_in[7];
    const float* cw   = (const float*)d_in[8];
    const float* cb   = (const float*)d_in[9];
    const float* pw   = (const float*)d_in[10];
    const float* pb   = (const float*)d_in[11];
    const float* qw   = (const float*)d_in[12];
    const float* qb   = (const float*)d_in[13];
    const float* kw   = (const float*)d_in[14];
    const float* kb   = (const float*)d_in[15];
    const float* vw   = (const float*)d_in[16];
    const float* vb   = (const float*)d_in[17];
    const float* ow   = (const float*)d_in[18];
    const float* ob   = (const float*)d_in[19];
    const float* ln0g = (const float*)d_in[20];
    const float* ln0b = (const float*)d_in[21];
    const float* ln1g = (const float*)d_in[22];
    const float* ln1b = (const float*)d_in[23];
    const float* f1w  = (const float*)d_in[24];
    const float* f1b  = (const float*)d_in[25];
    const float* f2w  = (const float*)d_in[26];
    const float* f2b  = (const float*)d_in[27];
    float* out = (float*)d_out;

    float *gx, *gy, *gq, *gk, *gv, *gatt, *gh;
    cudaGetSymbolAddress((void**)&gx,   g_x);
    cudaGetSymbolAddress((void**)&gy,   g_y);
    cudaGetSymbolAddress((void**)&gq,   g_q);
    cudaGetSymbolAddress((void**)&gk,   g_k);
    cudaGetSymbolAddress((void**)&gv,   g_v);
    cudaGetSymbolAddress((void**)&gatt, g_att);
    cudaGetSymbolAddress((void**)&gh,   g_h);
    cudaFuncSetAttribute(flash_attn, cudaFuncAttributeMaxDynamicSharedMemorySize,
                         FLASH_SMEM);

    // ---- prep: x = prenet( x + cond(spk) + f0conv(norm_f0) ) * mask ----
    conv_gemm<1, false, false, true ><<<dim3(T / 64, C / 64, B), 256>>>(
        spk, cw, cb, x, nullptr, gy, S, 0);
    add_f0<<<dim3(T / 256, C, B), 256>>>(f0, f0w, f0b, gy);
    conv_gemm<3, false, true, false><<<dim3(T / 64, C / 64, B), 256>>>(
        gy, prw, prb, nullptr, mask, gx, C, 1);

    for (int l = 0; l < L; l++) {
        const float* qwl = qw + (size_t)l * C * C;
        const float* kwl = kw + (size_t)l * C * C;
        const float* vwl = vw + (size_t)l * C * C;
        const float* owl = ow + (size_t)l * C * C;

        conv_gemm<1, false, false, false><<<dim3(T / 64, C / 64, B), 256>>>(
            gx, qwl, qb + l * C, nullptr, nullptr, gq, C, 0);
        conv_gemm<1, false, false, false><<<dim3(T / 64, C / 64, B), 256>>>(
            gx, kwl, kb + l * C, nullptr, nullptr, gk, C, 0);
        conv_gemm<1, false, false, false><<<dim3(T / 64, C / 64, B), 256>>>(
            gx, vwl, vb + l * C, nullptr, nullptr, gv, C, 0);

        flash_attn<<<dim3(T / 64, B * H), 256, FLASH_SMEM>>>(gq, gk, gv, gatt);

        conv_gemm<1, false, false, false><<<dim3(T / 64, C / 64, B), 256>>>(
            gatt, owl, ob + l * C, nullptr, nullptr, gy, C, 0);
        add_ln<<<dim3(T / 32, B), dim3(32, 8)>>>(gx, gy, ln0g + l * C, ln0b + l * C, gx);

        conv_gemm<3, true, false, false><<<dim3(T / 64, FC / 64, B), 256>>>(
            gx, f1w + (size_t)l * FC * C * 3, f1b + l * FC, nullptr, nullptr, gh, C, 2);
        conv_gemm<3, false, true, false><<<dim3(T / 64, C / 64, B), 256>>>(
            gh, f2w + (size_t)l * C * FC * 3, f2b + l * C, nullptr, mask, gy, FC, 2);
        add_ln<<<dim3(T / 32, B), dim3(32, 8)>>>(gx, gy, ln1g + l * C, ln1b + l * C, gx);
    }

    proj_out<<<dim3(T / 256, B), 256>>>(gx, pw, pb, mask, out);
}

// round 4
// speedup vs baseline: 1.9911x; 1.9911x over previous
#include <cuda_runtime.h>
#include <cuda_bf16.h>
#include <cstdint>
#include <cstddef>

// ---------------- problem constants ----------------
static constexpr int B  = 4;
static constexpr int C  = 512;
static constexpr int T  = 2048;
static constexpr int H  = 8;
static constexpr int FC = 2048;
static constexpr int L  = 6;
static constexpr int S  = 256;
static constexpr int DK = 64;

// ---------------- device scratch ----------------
__device__ float g_x  [B * C  * T];
__device__ float g_y  [B * C  * T];
__device__ float g_q  [B * C  * T];
__device__ float g_k  [B * C  * T];
__device__ float g_v  [B * C  * T];
__device__ float g_att[B * C  * T];
__device__ float g_h  [B * FC * T];

// ---------------- helpers ----------------
// pack two floats as bf16x2: low half = a (even k), high half = b (odd k)
__device__ __forceinline__ uint32_t pack_bf2(float a, float b) {
    uint32_t r;
    asm("cvt.rn.bf16x2.f32 %0, %1, %2;" : "=r"(r) : "f"(b), "f"(a));
    return r;
}
__device__ __forceinline__ float bf_hi_val(float v) {
    // value of bf16(v) as float
    __nv_bfloat16 h = __float2bfloat16_rn(v);
    return __bfloat162float(h);
}
__device__ __forceinline__ void mma_bf16(float* d, const uint32_t* a, const uint32_t* b) {
    asm volatile("mma.sync.aligned.m16n8k16.row.col.f32.bf16.bf16.f32 "
        "{%0,%1,%2,%3}, {%4,%5,%6,%7}, {%8,%9}, {%0,%1,%2,%3};"
        : "+f"(d[0]), "+f"(d[1]), "+f"(d[2]), "+f"(d[3])
        : "r"(a[0]), "r"(a[1]), "r"(a[2]), "r"(a[3]), "r"(b[0]), "r"(b[1]));
}

// ================= bf16x2-split mma.sync conv-GEMM =================
// Y[b,o,t] = sum_{c,kk} W[o,c,kk] * X[b,c,t+kk-PL]   (+bias, opt relu/mask/addsrc)
// CTA: M=128 (Cout) x N=128 (t). 8 warps in 2(m) x 4(n); warp tile 64x32.
// K chunked by 32 (=16 packed k2 rows). Operands split hi/lo bf16, product
// approximated by Ah*Bh + Ah*Bl + Al*Bh  (error ~2^-16 per term).
static constexpr int KSTR = 136;   // uint32 words per k2 row (bank-conflict-free)

template <int KW, int PL, bool RELU, bool DOMASK, bool ADDSRC>
__global__ __launch_bounds__(256, 2) void mma_gemm(
    const float* __restrict__ X, const float* __restrict__ W,
    const float* __restrict__ bias, const float* __restrict__ mask,
    const float* __restrict__ src, float* __restrict__ Y,
    int Cin, int Cout)
{
    __shared__ uint32_t Ah[16 * KSTR];   // [k2][m] packed bf16x2 (k even|odd)
    __shared__ uint32_t Al[16 * KSTR];
    __shared__ uint32_t Bh[16 * KSTR];   // [k2][n]
    __shared__ uint32_t Bl[16 * KSTR];

    const int tid  = threadIdx.x;
    const int lane = tid & 31;
    const int wid  = tid >> 5;
    const int mw   = wid & 1;            // warp m index (0..1)
    const int nw   = wid >> 1;           // warp n index (0..3)
    const int gid  = lane >> 2;          // groupID
    const int tig  = lane & 3;           // threadID in group

    const int b    = blockIdx.z;
    const int om   = blockIdx.y * 128;
    const int tn0  = blockIdx.x * 128;
    const int KTOT = Cin * KW;

    const float* __restrict__ Xb = X + (size_t)b * Cin * T;

    float acc[4][4][4];
#pragma unroll
    for (int i = 0; i < 4; i++)
#pragma unroll
        for (int j = 0; j < 4; j++)
#pragma unroll
            for (int r = 0; r < 4; r++) acc[i][j][r] = 0.f;

    const int nchunks = KTOT >> 5;
    for (int ch = 0; ch < nchunks; ch++) {
        const int k0 = ch << 5;

        // ---- A tile: W[om+m][k0 + 4q .. +3] -> Ah/Al[k2][m], k2 = 2q, 2q+1 ----
#pragma unroll
        for (int it = 0; it < 4; it++) {
            int quad = it * 256 + tid;          // 1024 quads
            int m  = quad & 127;
            int kq = quad >> 7;                 // 0..7
            float4 w4 = *(const float4*)(W + (size_t)(om + m) * KTOT + k0 + kq * 4);
            float hx = bf_hi_val(w4.x), hy = bf_hi_val(w4.y);
            float hz = bf_hi_val(w4.z), hw = bf_hi_val(w4.w);
            Ah[(2 * kq + 0) * KSTR + m] = pack_bf2(hx, hy);
            Ah[(2 * kq + 1) * KSTR + m] = pack_bf2(hz, hw);
            Al[(2 * kq + 0) * KSTR + m] = pack_bf2(w4.x - hx, w4.y - hy);
            Al[(2 * kq + 1) * KSTR + m] = pack_bf2(w4.z - hz, w4.w - hw);
        }
        // ---- B tile: im2col X -> Bh/Bl[k2][n]; word = (k even, k odd) per column n ----
#pragma unroll
        for (int r = 0; r < 2; r++) {
            int k2r = wid * 2 + r;              // 0..15
            int ka  = k0 + 2 * k2r;
            int kbp = ka + 1;
            int ca, da, cb, db;
            if (KW == 1) { ca = ka; da = 0; cb = kbp; db = 0; }
            else {
                ca = ka / 3;  da = (ka  - 3 * ca) - PL;
                cb = kbp / 3; db = (kbp - 3 * cb) - PL;
            }
            const float* xra = Xb + (size_t)ca * T;
            const float* xrb = Xb + (size_t)cb * T;
            int tbase = tn0 + lane * 4;
            float va[4], vb[4];
#pragma unroll
            for (int j = 0; j < 4; j++) {
                int ta = tbase + j + da;
                int tb = tbase + j + db;
                va[j] = ((unsigned)ta < (unsigned)T) ? xra[ta] : 0.f;
                vb[j] = ((unsigned)tb < (unsigned)T) ? xrb[tb] : 0.f;
            }
#pragma unroll
            for (int j = 0; j < 4; j++) {
                float ha = bf_hi_val(va[j]);
                float hb = bf_hi_val(vb[j]);
                Bh[k2r * KSTR + lane * 4 + j] = pack_bf2(ha, hb);
                Bl[k2r * KSTR + lane * 4 + j] = pack_bf2(va[j] - ha, vb[j] - hb);
            }
        }
        __syncthreads();

        // ---- 2 k-steps of 16 ----
#pragma unroll
        for (int ks = 0; ks < 2; ks++) {
            const int k2a = ks * 8 + tig;
            const int k2b = ks * 8 + 4 + tig;
            uint32_t bfh[4][2], bfl[4][2];
#pragma unroll
            for (int nt = 0; nt < 4; nt++) {
                int n = nw * 32 + nt * 8 + gid;
                bfh[nt][0] = Bh[k2a * KSTR + n];
                bfh[nt][1] = Bh[k2b * KSTR + n];
                bfl[nt][0] = Bl[k2a * KSTR + n];
                bfl[nt][1] = Bl[k2b * KSTR + n];
            }
#pragma unroll
            for (int mt = 0; mt < 4; mt++) {
                int m = mw * 64 + mt * 16 + gid;
                uint32_t afh[4], afl[4];
                afh[0] = Ah[k2a * KSTR + m];
                afh[1] = Ah[k2a * KSTR + m + 8];
                afh[2] = Ah[k2b * KSTR + m];
                afh[3] = Ah[k2b * KSTR + m + 8];
                afl[0] = Al[k2a * KSTR + m];
                afl[1] = Al[k2a * KSTR + m + 8];
                afl[2] = Al[k2b * KSTR + m];
                afl[3] = Al[k2b * KSTR + m + 8];
#pragma unroll
                for (int nt = 0; nt < 4; nt++) {
                    mma_bf16(acc[mt][nt], afh, bfh[nt]);
                    mma_bf16(acc[mt][nt], afh, bfl[nt]);
                    mma_bf16(acc[mt][nt], afl, bfh[nt]);
                }
            }
        }
        __syncthreads();
    }

    // ---- epilogue ----
#pragma unroll
    for (int mt = 0; mt < 4; mt++) {
        int o0 = om + mw * 64 + mt * 16 + gid;
        float b0 = bias[o0];
        float b1 = bias[o0 + 8];
#pragma unroll
        for (int nt = 0; nt < 4; nt++) {
            int t0 = tn0 + nw * 32 + nt * 8 + 2 * tig;
            float m0 = 1.f, m1 = 1.f;
            if (DOMASK) {
                m0 = mask[(size_t)b * T + t0];
                m1 = mask[(size_t)b * T + t0 + 1];
            }
            float v0 = acc[mt][nt][0] + b0;
            float v1 = acc[mt][nt][1] + b0;
            float v2 = acc[mt][nt][2] + b1;
            float v3 = acc[mt][nt][3] + b1;
            if (RELU) {
                v0 = fmaxf(v0, 0.f); v1 = fmaxf(v1, 0.f);
                v2 = fmaxf(v2, 0.f); v3 = fmaxf(v3, 0.f);
            }
            size_t oi0 = ((size_t)b * Cout + o0)     * T + t0;
            size_t oi1 = ((size_t)b * Cout + o0 + 8) * T + t0;
            if (ADDSRC) {
                float2 s0 = *(const float2*)(src + oi0);
                float2 s1 = *(const float2*)(src + oi1);
                v0 += s0.x; v1 += s0.y; v2 += s1.x; v3 += s1.y;
            }
            if (DOMASK) { v0 *= m0; v1 *= m1; v2 *= m0; v3 *= m1; }
            *(float2*)(Y + oi0) = make_float2(v0, v1);
            *(float2*)(Y + oi1) = make_float2(v2, v3);
        }
    }
}

// ---------------- f0 prenet (Cin=1, K=3, pad 1,1) added in-place ----------------
__global__ void add_f0(const float* __restrict__ f0, const float* __restrict__ w,
                       const float* __restrict__ fb, float* __restrict__ y)
{
    int t = blockIdx.x * 256 + threadIdx.x;
    int c = blockIdx.y;
    int b = blockIdx.z;
    float fm1 = (t - 1 >= 0) ? f0[(size_t)b * T + t - 1] : 0.f;
    float fc0 = f0[(size_t)b * T + t];
    float fp1 = (t + 1 < T) ? f0[(size_t)b * T + t + 1] : 0.f;
    float v = w[c * 3 + 0] * fm1 + w[c * 3 + 1] * fc0 + w[c * 3 + 2] * fp1 + fb[c];
    y[((size_t)b * C + c) * T + t] += v;
}

// ---------------- fused residual-add + LayerNorm over channel dim ----------------
__global__ void add_ln(const float* __restrict__ x, const float* __restrict__ y,
                       const float* __restrict__ g, const float* __restrict__ be,
                       float* __restrict__ out)
{
    __shared__ float red0[8][32];
    __shared__ float red1[8][32];
    __shared__ float smv[2][32];
    const int tx = threadIdx.x, ty = threadIdx.y;
    const int t = blockIdx.x * 32 + tx;
    const int b = blockIdx.y;
    const size_t base = (size_t)b * C * T + t;

    float s = 0.f, sq = 0.f;
    for (int c = ty; c < C; c += 8) {
        float v = x[base + (size_t)c * T] + y[base + (size_t)c * T];
        s += v; sq += v * v;
    }
    red0[ty][tx] = s; red1[ty][tx] = sq;
    __syncthreads();
    if (ty == 0) {
#pragma unroll
        for (int i = 1; i < 8; i++) { s += red0[i][tx]; sq += red1[i][tx]; }
        float mean = s * (1.f / C);
        float var  = sq * (1.f / C) - mean * mean;
        smv[0][tx] = mean;
        smv[1][tx] = rsqrtf(var + 1e-5f);
    }
    __syncthreads();
    float mean = smv[0][tx], rstd = smv[1][tx];
    for (int c = ty; c < C; c += 8) {
        float v = x[base + (size_t)c * T] + y[base + (size_t)c * T];
        out[base + (size_t)c * T] = (v - mean) * rstd * g[c] + be[c];
    }
}

// ---------------- fused causal flash attention (fp32) ----------------
static constexpr int FLASH_SMEM = (64 * 64 + 64 * 68 + 64 * 68) * 4;

__global__ __launch_bounds__(256) void flash_attn(
    const float* __restrict__ q, const float* __restrict__ k,
    const float* __restrict__ v, float* __restrict__ o)
{
    extern __shared__ float sm[];
    float* Qs = sm;
    float* Ks = sm + 64 * 64;
    float* Vt = Ks + 64 * 68;
    float* Ss = Ks;

    const int tid  = threadIdx.x;
    const int lane = tid & 31;
    const int warp = tid >> 5;
    const int mb   = blockIdx.x;
    const int m0   = mb * 64;
    const int bh   = blockIdx.y;
    const int b    = bh >> 3;
    const int h    = bh & 7;
    const size_t base = ((size_t)b * C + (size_t)h * DK) * T;
    const float* __restrict__ qp = q + base;
    const float* __restrict__ kp = k + base;
    const float* __restrict__ vp = v + base;

    for (int idx = tid; idx < 64 * 64; idx += 256) {
        int d = idx >> 6, tt = idx & 63;
        Qs[tt * 64 + d] = qp[(size_t)d * T + m0 + tt] * 0.125f;
    }

    float mI[8], lI[8], a0[8], a1[8];
#pragma unroll
    for (int r = 0; r < 8; r++) { mI[r] = -1e30f; lI[r] = 0.f; a0[r] = 0.f; a1[r] = 0.f; }
    const int r0 = warp * 8;

    for (int kbk = 0; kbk <= mb; kbk++) {
        const int kn0 = kbk * 64;
        __syncthreads();
        for (int idx = tid; idx < 64 * 64; idx += 256) {
            int d = idx >> 6, j = idx & 63;
            Ks[j * 68 + d] = kp[(size_t)d * T + kn0 + j];
            Vt[d * 68 + j] = vp[(size_t)d * T + kn0 + j];
        }
        __syncthreads();

        float sc0[8], sc1[8];
#pragma unroll
        for (int r = 0; r < 8; r++) {
            int rr = r0 + r;
            float s0 = 0.f, s1 = 0.f;
#pragma unroll
            for (int d = 0; d < 64; d += 4) {
                float4 q4 = *(const float4*)&Qs[rr * 64 + d];
                float4 ka = *(const float4*)&Ks[lane * 68 + d];
                float4 kb = *(const float4*)&Ks[(lane + 32) * 68 + d];
                s0 += q4.x * ka.x + q4.y * ka.y + q4.z * ka.z + q4.w * ka.w;
                s1 += q4.x * kb.x + q4.y * kb.y + q4.z * kb.z + q4.w * kb.w;
            }
            int tg = m0 + rr;
            if (kn0 + lane      > tg) s0 = -1e4f;
            if (kn0 + lane + 32 > tg) s1 = -1e4f;
            sc0[r] = s0; sc1[r] = s1;
        }
        __syncthreads();

#pragma unroll
        for (int r = 0; r < 8; r++) {
            int rr = r0 + r;
            float mx = fmaxf(sc0[r], sc1[r]);
#pragma unroll
            for (int off = 16; off; off >>= 1)
                mx = fmaxf(mx, __shfl_xor_sync(0xffffffffu, mx, off));
            float mnew = fmaxf(mI[r], mx);
            float p0 = __expf(sc0[r] - mnew);
            float p1 = __expf(sc1[r] - mnew);
            float ps = p0 + p1;
#pragma unroll
            for (int off = 16; off; off >>= 1)
                ps += __shfl_xor_sync(0xffffffffu, ps, off);
            float corr = __expf(mI[r] - mnew);
            lI[r] = lI[r] * corr + ps;
            mI[r] = mnew;
            a0[r] *= corr; a1[r] *= corr;
            Ss[rr * 68 + lane]      = p0;
            Ss[rr * 68 + lane + 32] = p1;
        }
        __syncwarp();

#pragma unroll
        for (int r = 0; r < 8; r++) {
            int rr = r0 + r;
            float acc0 = 0.f, acc1 = 0.f;
#pragma unroll
            for (int j = 0; j < 64; j += 4) {
                float4 p4 = *(const float4*)&Ss[rr * 68 + j];
                float4 va = *(const float4*)&Vt[lane * 68 + j];
                float4 vb = *(const float4*)&Vt[(lane + 32) * 68 + j];
                acc0 += p4.x * va.x + p4.y * va.y + p4.z * va.z + p4.w * va.w;
                acc1 += p4.x * vb.x + p4.y * vb.y + p4.z * vb.z + p4.w * vb.w;
            }
            a0[r] += acc0; a1[r] += acc1;
        }
    }

#pragma unroll
    for (int r = 0; r < 8; r++) {
        int rr = r0 + r;
        float inv = 1.f / lI[r];
        o[base + (size_t)lane        * T + m0 + rr] = a0[r] * inv;
        o[base + (size_t)(lane + 32) * T + m0 + rr] = a1[r] * inv;
    }
}

// ---------------- final 1-channel projection ----------------
__global__ void proj_out(const float* __restrict__ x, const float* __restrict__ w,
                         const float* __restrict__ pb, const float* __restrict__ mask,
                         float* __restrict__ out)
{
    int t = blockIdx.x * 256 + threadIdx.x;
    int b = blockIdx.y;
    float s = pb[0];
    const float* xb = x + (size_t)b * C * T;
    for (int c = 0; c < C; c++)
        s += w[c] * xb[(size_t)c * T + t];
    out[(size_t)b * T + t] = s * mask[(size_t)b * T + t];
}

// ---------------- launch ----------------
extern "C" void kernel_launch(void* const* d_in, const int* in_sizes, int n_in,
                              void* d_out, int out_size)
{
    const float* x    = (const float*)d_in[0];
    const float* f0   = (const float*)d_in[1];
    const float* mask = (const float*)d_in[2];
    const float* spk  = (const float*)d_in[3];
    const float* prw  = (const float*)d_in[4];
    const float* prb  = (const float*)d_in[5];
    const float* f0w  = (const float*)d_in[6];
    const float* f0b  = (const float*)d_in[7];
    const float* cw   = (const float*)d_in[8];
    const float* cb   = (const float*)d_in[9];
    const float* pw   = (const float*)d_in[10];
    const float* pb   = (const float*)d_in[11];
    const float* qw   = (const float*)d_in[12];
    const float* qb   = (const float*)d_in[13];
    const float* kw   = (const float*)d_in[14];
    const float* kb   = (const float*)d_in[15];
    const float* vw   = (const float*)d_in[16];
    const float* vb   = (const float*)d_in[17];
    const float* ow   = (const float*)d_in[18];
    const float* ob   = (const float*)d_in[19];
    const float* ln0g = (const float*)d_in[20];
    const float* ln0b = (const float*)d_in[21];
    const float* ln1g = (const float*)d_in[22];
    const float* ln1b = (const float*)d_in[23];
    const float* f1w  = (const float*)d_in[24];
    const float* f1b  = (const float*)d_in[25];
    const float* f2w  = (const float*)d_in[26];
    const float* f2b  = (const float*)d_in[27];
    float* out = (float*)d_out;

    float *gx, *gy, *gq, *gk, *gv, *gatt, *gh;
    cudaGetSymbolAddress((void**)&gx,   g_x);
    cudaGetSymbolAddress((void**)&gy,   g_y);
    cudaGetSymbolAddress((void**)&gq,   g_q);
    cudaGetSymbolAddress((void**)&gk,   g_k);
    cudaGetSymbolAddress((void**)&gv,   g_v);
    cudaGetSymbolAddress((void**)&gatt, g_att);
    cudaGetSymbolAddress((void**)&gh,   g_h);

    cudaFuncSetAttribute(flash_attn, cudaFuncAttributeMaxDynamicSharedMemorySize, FLASH_SMEM);

    // ---- prep: gy = x + cond(spk); gy += f0conv; gx = prenet(gy) * mask ----
    mma_gemm<1,0,false,false,true ><<<dim3(T/128, C/128, B), 256>>>(
        spk, cw, cb, nullptr, x, gy, S, C);
    add_f0<<<dim3(T/256, C, B), 256>>>(f0, f0w, f0b, gy);
    mma_gemm<3,1,false,true ,false><<<dim3(T/128, C/128, B), 256>>>(
        gy, prw, prb, mask, nullptr, gx, C, C);

    for (int l = 0; l < L; l++) {
        mma_gemm<1,0,false,false,false><<<dim3(T/128, C/128, B), 256>>>(
            gx, qw + (size_t)l*C*C, qb + l*C, nullptr, nullptr, gq, C, C);
        mma_gemm<1,0,false,false,false><<<dim3(T/128, C/128, B), 256>>>(
            gx, kw + (size_t)l*C*C, kb + l*C, nullptr, nullptr, gk, C, C);
        mma_gemm<1,0,false,false,false><<<dim3(T/128, C/128, B), 256>>>(
            gx, vw + (size_t)l*C*C, vb + l*C, nullptr, nullptr, gv, C, C);

        flash_attn<<<dim3(T/64, B*H), 256, FLASH_SMEM>>>(gq, gk, gv, gatt);

        mma_gemm<1,0,false,false,false><<<dim3(T/128, C/128, B), 256>>>(
            gatt, ow + (size_t)l*C*C, ob + l*C, nullptr, nullptr, gy, C, C);
        add_ln<<<dim3(T/32, B), dim3(32, 8)>>>(gx, gy, ln0g + l*C, ln0b + l*C, gx);

        mma_gemm<3,2,true ,false,false><<<dim3(T/128, FC/128, B), 256>>>(
            gx, f1w + (size_t)l*FC*C*3, f1b + l*FC, nullptr, nullptr, gh, C, FC);
        mma_gemm<3,2,false,true ,false><<<dim3(T/128, C/128, B), 256>>>(
            gh, f2w + (size_t)l*C*FC*3, f2b + l*C, mask, nullptr, gy, FC, C);
        add_ln<<<dim3(T/32, B), dim3(32, 8)>>>(gx, gy, ln1g + l*C, ln1b + l*C, gx);
    }

    proj_out<<<dim3(T/256, B), 256>>>(gx, pw, pb, mask, out);
}